// round 9
// baseline (speedup 1.0000x reference)
#include <cuda_runtime.h>
#include <cuda_fp16.h>
#include <math.h>
#include <stdint.h>

#define NU 100000
#define NI 100000
#define NE 300000
#define NROWS (NU + NI)
#define NTILES 1563
#define NPAD (NTILES * 128)
#define G3 384
#define MDIM 512

__device__ int    d_lastU[NU];
__device__ int    d_lastV[NI];
__device__ __half d_hWi[G3 * MDIM];
__device__ __half d_hWh[G3 * 128];
__device__ __half d_H[(size_t)NPAD * 128];
__device__ float  d_G1[(size_t)NROWS * G3];
__device__ float  d_G2[(size_t)NROWS * G3];

// ---------------------------------------------------------------------------
__global__ void k_init_last() {
    int i = blockIdx.x * blockDim.x + threadIdx.x;
    if (i < NU) d_lastU[i] = -1;
    if (i < NI) d_lastV[i] = -1;
}

__global__ void k_scan_edges(const int* __restrict__ src, const int* __restrict__ dst) {
    int i = blockIdx.x * blockDim.x + threadIdx.x;
    if (i < NE) {
        atomicMax(&d_lastU[src[i]], i);
        atomicMax(&d_lastV[dst[i]], i);
    }
}

__global__ void k_cvt_w(const float* __restrict__ Wi, const float* __restrict__ Wh) {
    int i = blockIdx.x * blockDim.x + threadIdx.x;
    if (i < G3 * MDIM) d_hWi[i] = __float2half(Wi[i]);
    if (i < G3 * 128)  d_hWh[i] = __float2half(Wh[i]);
}

// ---------------------------------------------------------------------------
__device__ __forceinline__ uint32_t smem_u32(const void* p) {
    uint32_t a;
    asm("{ .reg .u64 t; cvta.to.shared.u64 t, %1; cvt.u32.u64 %0, t; }" : "=r"(a) : "l"(p));
    return a;
}
__device__ __forceinline__ void cp16(uint32_t dst, const void* src) {
    asm volatile("cp.async.cg.shared.global [%0], [%1], 16;"
                 :: "r"(dst), "l"(src) : "memory");
}
#define CP_COMMIT() asm volatile("cp.async.commit_group;" ::: "memory")
#define CP_WAIT2()  asm volatile("cp.async.wait_group 2;" ::: "memory")

__device__ __forceinline__ void ldsm4(uint32_t& r0, uint32_t& r1, uint32_t& r2,
                                      uint32_t& r3, uint32_t a) {
    asm volatile("ldmatrix.sync.aligned.m8n8.x4.shared.b16 {%0,%1,%2,%3}, [%4];"
                 : "=r"(r0), "=r"(r1), "=r"(r2), "=r"(r3) : "r"(a));
}
__device__ __forceinline__ void mma_f16(float c[4], uint32_t a0, uint32_t a1,
                                        uint32_t a2, uint32_t a3,
                                        uint32_t b0, uint32_t b1) {
    asm volatile(
        "mma.sync.aligned.m16n8k16.row.col.f32.f16.f16.f32 "
        "{%0,%1,%2,%3}, {%4,%5,%6,%7}, {%8,%9}, {%0,%1,%2,%3};"
        : "+f"(c[0]), "+f"(c[1]), "+f"(c[2]), "+f"(c[3])
        : "r"(a0), "r"(a1), "r"(a2), "r"(a3), "r"(b0), "r"(b1));
}
__device__ __forceinline__ uint32_t h2u(__half2 h) { return *(uint32_t*)&h; }
__device__ __forceinline__ float sigf(float x) { return 1.f / (1.f + expf(-x)); }

// swizzled byte offset within one [128 rows x 32 halves] 8KB chunk
__device__ __forceinline__ uint32_t sw_off(int m, int u) {
    return (uint32_t)((m << 6) + (((u ^ ((m >> 1) & 3)) & 3) << 4));
}

// ===========================================================================
// Kernel 1: fused gather/build-X (smem) + d_H emit + GEMM1 -> d_G1
// 512 threads (16 warps: 4M x 4N). CTA: 128 rows x 384 cols, continuous
// 48-chunk B pipeline. smem: X 128KB | B 32KB | meta.
#define K1_XB    0
#define K1_BB    131072
#define K1_META  163840
#define K1_SMEM  (K1_META + 1536)

__global__ __launch_bounds__(512, 1)
void k_gemm1f(const float* __restrict__ si, const float* __restrict__ sj,
              const float* __restrict__ t,  const float* __restrict__ efeat,
              const int* __restrict__ src,  const int* __restrict__ dst,
              const float* __restrict__ freq) {
    extern __shared__ char smraw[];
    const uint32_t sbX = smem_u32(smraw) + K1_XB;
    const uint32_t sbB = smem_u32(smraw) + K1_BB;
    int*   s_le = (int*)(smraw + K1_META);
    int*   s_ot = s_le + 128;
    float* s_tv = (float*)(s_ot + 128);

    const int tid  = threadIdx.x;
    const int lane = tid & 31;
    const int w    = tid >> 5;
    const int wm   = w & 3;
    const int wn   = w >> 2;
    const int g    = lane >> 2;
    const int tg   = lane & 3;
    const int m0   = blockIdx.x * 128;

    // B cp.async loader slots
    const int brow = tid >> 2;
    const int bu   = tid & 3;
    const uint32_t dB = sw_off(brow, bu);

    // B prologue: 3 chunks of the 48-chunk stream, issued BEFORE the build
    // phase so the LDGSTS overlap the gather latency.
#pragma unroll
    for (int s = 0; s < 3; ++s) {
        const __half* p = d_hWi + (size_t)brow * MDIM + s * 32 + bu * 8;  // nt=0
        cp16(sbB + s * 8192 + dB, p);
        CP_COMMIT();
    }

    if (tid < 128) {
        int gr = m0 + tid;
        int le = -1, ot = 0; float tv = 0.f;
        if (gr < NU) {
            le = d_lastU[gr];
            if (le >= 0) { ot = dst[le]; tv = t[le]; }
        } else if (gr < NROWS) {
            le = d_lastV[gr - NU];
            if (le >= 0) { ot = src[le]; tv = t[le]; }
        }
        s_le[tid] = le; s_ot[tid] = ot; s_tv[tid] = tv;
    }
    __syncthreads();

    // ---- build X in smem (+ emit d_H on sec==1)
    {
        const int bm = tid >> 6;        // 0..7
        const int u  = tid & 63;
        const int sec  = u >> 4;        // 0..3
        const int colu = (u & 15) * 8;
#pragma unroll 1
        for (int i = 0; i < 16; ++i) {
            const int m  = bm + 8 * i;
            const int gr = m0 + m;
            const int le = s_le[m];
            float v[8];
            if (sec == 1) {
                if (gr < NROWS) {
                    const float* p = ((gr < NU) ? si + (size_t)gr * 128
                                                : sj + (size_t)(gr - NU) * 128) + colu;
                    float4 a = __ldg((const float4*)p);
                    float4 b = __ldg((const float4*)(p + 4));
                    v[0]=a.x; v[1]=a.y; v[2]=a.z; v[3]=a.w;
                    v[4]=b.x; v[5]=b.y; v[6]=b.z; v[7]=b.w;
                    // emit fp16 h row chunk for GEMM2
                    uint4 hh;
                    hh.x = h2u(__floats2half2_rn(v[0], v[1]));
                    hh.y = h2u(__floats2half2_rn(v[2], v[3]));
                    hh.z = h2u(__floats2half2_rn(v[4], v[5]));
                    hh.w = h2u(__floats2half2_rn(v[6], v[7]));
                    *(uint4*)(d_H + (size_t)gr * 128 + colu) = hh;
                    if (le < 0) {
#pragma unroll
                        for (int k = 0; k < 8; ++k) v[k] = 0.f;
                    }
                } else {
#pragma unroll
                    for (int k = 0; k < 8; ++k) v[k] = 0.f;
                }
            } else if (le < 0) {
#pragma unroll
                for (int k = 0; k < 8; ++k) v[k] = 0.f;
            } else if (sec == 2) {
                const float tv = s_tv[m];
#pragma unroll
                for (int k = 0; k < 8; ++k) v[k] = __cosf(tv * __ldg(freq + colu + k));
            } else {
                const float* p;
                if (sec == 0) {
                    const int ot = s_ot[m];
                    p = ((gr < NU) ? sj : si) + (size_t)ot * 128 + colu;
                } else {
                    p = efeat + (size_t)le * 128 + colu;
                }
                float4 a = __ldg((const float4*)p);
                float4 b = __ldg((const float4*)(p + 4));
                v[0]=a.x; v[1]=a.y; v[2]=a.z; v[3]=a.w;
                v[4]=b.x; v[5]=b.y; v[6]=b.z; v[7]=b.w;
            }
            uint32_t h0 = h2u(__floats2half2_rn(v[0], v[1]));
            uint32_t h1 = h2u(__floats2half2_rn(v[2], v[3]));
            uint32_t h2_ = h2u(__floats2half2_rn(v[4], v[5]));
            uint32_t h3 = h2u(__floats2half2_rn(v[6], v[7]));
            uint32_t addr = sbX + (u >> 2) * 8192 + sw_off(m, u & 3);
            asm volatile("st.shared.v4.b32 [%0], {%1,%2,%3,%4};"
                         :: "r"(addr), "r"(h0), "r"(h1), "r"(h2_), "r"(h3) : "memory");
        }
    }
    __syncthreads();

    // ---- ldmatrix per-lane offsets
    uint32_t offA[2][2], offB[2][2];
    {
        const int mr = lane & 15;
        const int uu = lane >> 4;
#pragma unroll
        for (int im = 0; im < 2; ++im)
#pragma unroll
            for (int kk = 0; kk < 2; ++kk)
                offA[im][kk] = sw_off(wm * 32 + im * 16 + mr, kk * 2 + uu);
#pragma unroll
        for (int j = 0; j < 2; ++j)
#pragma unroll
            for (int kk = 0; kk < 2; ++kk)
                offB[j][kk] = sw_off(wn * 32 + j * 16 + mr, kk * 2 + uu);
    }

    float acc[2][4][4];
#pragma unroll
    for (int i = 0; i < 2; ++i)
#pragma unroll
        for (int j = 0; j < 4; ++j)
#pragma unroll
            for (int c = 0; c < 4; ++c) acc[i][j][c] = 0.f;

    // ---- continuous 48-chunk pipeline (nt = gc>>4, c = gc&15)
#pragma unroll 1
    for (int gc = 0; gc < 48; ++gc) {
        CP_WAIT2();
        __syncthreads();
        if (gc + 3 < 48) {
            const int n = gc + 3;
            const __half* p = d_hWi + (size_t)((n >> 4) * 128 + brow) * MDIM +
                              (n & 15) * 32 + bu * 8;
            cp16(sbB + ((n & 3)) * 8192 + dB, p);
        }
        CP_COMMIT();

        const uint32_t xc  = sbX + (gc & 15) * 8192;
        const uint32_t stg = sbB + (gc & 3) * 8192;
#pragma unroll
        for (int kk = 0; kk < 2; ++kk) {
            uint32_t a[2][4], b[2][4];
#pragma unroll
            for (int im = 0; im < 2; ++im)
                ldsm4(a[im][0], a[im][1], a[im][2], a[im][3], xc + offA[im][kk]);
#pragma unroll
            for (int j = 0; j < 2; ++j)
                ldsm4(b[j][0], b[j][1], b[j][2], b[j][3], stg + offB[j][kk]);
#pragma unroll
            for (int im = 0; im < 2; ++im) {
                mma_f16(acc[im][0], a[im][0], a[im][1], a[im][2], a[im][3],
                        b[0][0], b[0][2]);
                mma_f16(acc[im][1], a[im][0], a[im][1], a[im][2], a[im][3],
                        b[0][1], b[0][3]);
                mma_f16(acc[im][2], a[im][0], a[im][1], a[im][2], a[im][3],
                        b[1][0], b[1][2]);
                mma_f16(acc[im][3], a[im][0], a[im][1], a[im][2], a[im][3],
                        b[1][1], b[1][3]);
            }
        }

        if ((gc & 15) == 15) {
            const int nt = gc >> 4;
#pragma unroll
            for (int im = 0; im < 2; ++im) {
#pragma unroll
                for (int in_ = 0; in_ < 4; ++in_) {
                    const int row = m0 + wm * 32 + im * 16 + g;
                    const int col = nt * 128 + wn * 32 + in_ * 8 + tg * 2;
                    if (row < NROWS)
                        *(float2*)(d_G1 + (size_t)row * G3 + col) =
                            make_float2(acc[im][in_][0], acc[im][in_][1]);
                    if (row + 8 < NROWS)
                        *(float2*)(d_G1 + (size_t)(row + 8) * G3 + col) =
                            make_float2(acc[im][in_][2], acc[im][in_][3]);
                    acc[im][in_][0] = acc[im][in_][1] = 0.f;
                    acc[im][in_][2] = acc[im][in_][3] = 0.f;
                }
            }
        }
    }
}

// ===========================================================================
// Kernel 2: GEMM2  d_G2 = H @ Wh^T  (R6-proven shape: 256 thr, 2 CTA/SM,
// 128x128 tile, BK=32, 4-stage cp.async, ldmatrix, warp tile 64x32)
#define STG_BYTES 16384
#define SMEM_TOT  (4 * STG_BYTES)

__global__ __launch_bounds__(256, 2)
void k_gemm2(void) {
    extern __shared__ char smraw[];
    const uint32_t sb = smem_u32(smraw);

    const int tid  = threadIdx.x;
    const int lane = tid & 31;
    const int w    = tid >> 5;
    const int wm   = w & 1;
    const int wn   = w >> 1;
    const int g    = lane >> 2;
    const int tg   = lane & 3;
    const int m0   = blockIdx.x * 128;
    const int n0   = blockIdx.y * 128;

    const int lrow = tid >> 1;
    const int u0   = (tid & 1) * 2;
    const __half* aP = d_H   + (size_t)(m0 + lrow) * 128 + u0 * 8;
    const __half* bP = d_hWh + (size_t)(n0 + lrow) * 128 + u0 * 8;
    const uint32_t dA0 = sw_off(lrow, u0);
    const uint32_t dA1 = sw_off(lrow, u0 + 1);

    uint32_t offA[4][2], offB[2][2];
    {
        const int mr = ((lane >> 3) & 1) * 8 + (lane & 7);
        const int uu = lane >> 4;
#pragma unroll
        for (int im = 0; im < 4; ++im)
#pragma unroll
            for (int kk = 0; kk < 2; ++kk)
                offA[im][kk] = sw_off(wm * 64 + im * 16 + mr, kk * 2 + uu);
#pragma unroll
        for (int j = 0; j < 2; ++j)
#pragma unroll
            for (int kk = 0; kk < 2; ++kk)
                offB[j][kk] = 8192u + sw_off(wn * 32 + j * 16 + mr, kk * 2 + uu);
    }

    float acc[4][4][4];
#pragma unroll
    for (int i = 0; i < 4; ++i)
#pragma unroll
        for (int j = 0; j < 4; ++j)
#pragma unroll
            for (int c = 0; c < 4; ++c) acc[i][j][c] = 0.f;

#pragma unroll
    for (int s = 0; s < 3; ++s) {
        const uint32_t st = sb + s * STG_BYTES;
        cp16(st + dA0,        aP + s * 32);
        cp16(st + dA1,        aP + s * 32 + 8);
        cp16(st + 8192 + dA0, bP + s * 32);
        cp16(st + 8192 + dA1, bP + s * 32 + 8);
        CP_COMMIT();
    }

#pragma unroll 1
    for (int c = 0; c < 4; ++c) {
        CP_WAIT2();
        __syncthreads();
        if (c + 3 < 4) {
            const uint32_t st = sb + ((c + 3) & 3) * STG_BYTES;
            cp16(st + dA0,        aP + (c + 3) * 32);
            cp16(st + dA1,        aP + (c + 3) * 32 + 8);
            cp16(st + 8192 + dA0, bP + (c + 3) * 32);
            cp16(st + 8192 + dA1, bP + (c + 3) * 32 + 8);
        }
        CP_COMMIT();

        const uint32_t stg = sb + (c & 3) * STG_BYTES;
#pragma unroll
        for (int kk = 0; kk < 2; ++kk) {
            uint32_t a[4][4], b[2][4];
#pragma unroll
            for (int im = 0; im < 4; ++im)
                ldsm4(a[im][0], a[im][1], a[im][2], a[im][3], stg + offA[im][kk]);
#pragma unroll
            for (int j = 0; j < 2; ++j)
                ldsm4(b[j][0], b[j][1], b[j][2], b[j][3], stg + offB[j][kk]);
#pragma unroll
            for (int im = 0; im < 4; ++im) {
                mma_f16(acc[im][0], a[im][0], a[im][1], a[im][2], a[im][3],
                        b[0][0], b[0][2]);
                mma_f16(acc[im][1], a[im][0], a[im][1], a[im][2], a[im][3],
                        b[0][1], b[0][3]);
                mma_f16(acc[im][2], a[im][0], a[im][1], a[im][2], a[im][3],
                        b[1][0], b[1][2]);
                mma_f16(acc[im][3], a[im][0], a[im][1], a[im][2], a[im][3],
                        b[1][1], b[1][3]);
            }
        }
    }

#pragma unroll
    for (int im = 0; im < 4; ++im) {
#pragma unroll
        for (int in_ = 0; in_ < 4; ++in_) {
            const int row = m0 + wm * 64 + im * 16 + g;
            const int col = n0 + wn * 32 + in_ * 8 + tg * 2;
            if (row < NROWS)
                *(float2*)(d_G2 + (size_t)row * G3 + col) =
                    make_float2(acc[im][in_][0], acc[im][in_][1]);
            if (row + 8 < NROWS)
                *(float2*)(d_G2 + (size_t)(row + 8) * G3 + col) =
                    make_float2(acc[im][in_][2], acc[im][in_][3]);
        }
    }
}

// ---------------------------------------------------------------------------
__global__ void k_combine(const float* __restrict__ si, const float* __restrict__ sj,
                          const float* __restrict__ bi, const float* __restrict__ bh,
                          float* __restrict__ out) {
    int r = blockIdx.x;
    int j = threadIdx.x;  // 0..127
    const float* g1 = d_G1 + (size_t)r * G3;
    const float* g2 = d_G2 + (size_t)r * G3;

    float h = (r < NU) ? si[(size_t)r * 128 + j] : sj[(size_t)(r - NU) * 128 + j];

    float gir = g1[j]       + bi[j];
    float giz = g1[j + 128] + bi[j + 128];
    float gin = g1[j + 256] + bi[j + 256];
    float ghr = g2[j]       + bh[j];
    float ghz = g2[j + 128] + bh[j + 128];
    float ghn = g2[j + 256] + bh[j + 256];

    float rr = sigf(gir + ghr);
    float zz = sigf(giz + ghz);
    float nn = tanhf(gin + rr * ghn);

    out[(size_t)r * 128 + j] = (1.f - zz) * nn + zz * h;
}

// ---------------------------------------------------------------------------
extern "C" void kernel_launch(void* const* d_in, const int* in_sizes, int n_in,
                              void* d_out, int out_size) {
    const float* si   = (const float*)d_in[0];
    const float* sj   = (const float*)d_in[1];
    const float* t    = (const float*)d_in[2];
    const float* ef   = (const float*)d_in[3];
    const int*   src  = (const int*)d_in[4];
    const int*   dst  = (const int*)d_in[5];
    const float* Wi   = (const float*)d_in[6];
    const float* Wh   = (const float*)d_in[7];
    const float* bi   = (const float*)d_in[8];
    const float* bh   = (const float*)d_in[9];
    const float* freq = (const float*)d_in[10];
    float* out = (float*)d_out;

    k_init_last<<<(NU + 255) / 256, 256>>>();
    k_scan_edges<<<(NE + 255) / 256, 256>>>(src, dst);
    k_cvt_w<<<(G3 * MDIM + 255) / 256, 256>>>(Wi, Wh);

    cudaFuncSetAttribute(k_gemm1f, cudaFuncAttributeMaxDynamicSharedMemorySize, K1_SMEM);
    k_gemm1f<<<NTILES, 512, K1_SMEM>>>(si, sj, t, ef, src, dst, freq);

    cudaFuncSetAttribute(k_gemm2, cudaFuncAttributeMaxDynamicSharedMemorySize, SMEM_TOT);
    dim3 grid2(NTILES, 3);
    k_gemm2<<<grid2, 256, SMEM_TOT>>>();

    k_combine<<<NROWS, 128>>>(si, sj, bi, bh, out);
}

// round 10
// speedup vs baseline: 1.2029x; 1.2029x over previous
#include <cuda_runtime.h>
#include <cuda_fp16.h>
#include <math.h>
#include <stdint.h>

#define NU 100000
#define NI 100000
#define NE 300000
#define NROWS (NU + NI)
#define NPAD 200064            // 1563 * 128
#define G3 384
#define MDIM 512

__device__ int    d_lastU[NU];
__device__ int    d_lastV[NI];
__device__ __half d_X[(size_t)NPAD * MDIM];   // mail fp16 (padded rows stay 0)
__device__ __half d_H[(size_t)NPAD * 128];    // h fp16
__device__ __half d_hWi[G3 * MDIM];
__device__ __half d_hWh[G3 * 128];
__device__ float  d_G1[(size_t)NROWS * G3];
__device__ float  d_G2[(size_t)NROWS * G3];

// ---------------------------------------------------------------------------
__global__ void k_init_last() {
    int i = blockIdx.x * blockDim.x + threadIdx.x;
    if (i < NU) d_lastU[i] = -1;
    if (i < NI) d_lastV[i] = -1;
}

__global__ void k_scan_edges(const int* __restrict__ src, const int* __restrict__ dst) {
    int i = blockIdx.x * blockDim.x + threadIdx.x;
    if (i < NE) {
        atomicMax(&d_lastU[src[i]], i);
        atomicMax(&d_lastV[dst[i]], i);
    }
}

__global__ void k_cvt_w(const float* __restrict__ Wi, const float* __restrict__ Wh) {
    int i = blockIdx.x * blockDim.x + threadIdx.x;
    if (i < G3 * MDIM) d_hWi[i] = __float2half(Wi[i]);
    if (i < G3 * 128)  d_hWh[i] = __float2half(Wh[i]);
}

__device__ __forceinline__ uint32_t h2u(__half2 h) { return *(uint32_t*)&h; }

// K2: build X rows (fp16, vectorized 8B stores) + H rows (fp16).
// One row per 128-thread block; thread covers 4 cols of one section.
__global__ void k_build_x(const float* __restrict__ si, const float* __restrict__ sj,
                          const float* __restrict__ t,  const float* __restrict__ efeat,
                          const int* __restrict__ src,  const int* __restrict__ dst,
                          const float* __restrict__ freq) {
    const int r   = blockIdx.x;
    const int tid = threadIdx.x;      // 0..127
    const int sec = tid >> 5;         // 0..3
    const int c4  = (tid & 31) * 4;   // col within section

    int le;
    const float* ownbase;
    const float* otherArr;
    if (r < NU) {
        le = d_lastU[r];
        ownbase = si + (size_t)r * 128;
        otherArr = sj;
    } else {
        le = d_lastV[r - NU];
        ownbase = sj + (size_t)(r - NU) * 128;
        otherArr = si;
    }

    float4 v;
    if (sec == 1) {
        v = __ldg((const float4*)(ownbase + c4));
        // emit h row chunk (always)
        uint2 hh;
        hh.x = h2u(__floats2half2_rn(v.x, v.y));
        hh.y = h2u(__floats2half2_rn(v.z, v.w));
        *(uint2*)(d_H + (size_t)r * 128 + c4) = hh;
        if (le < 0) v = make_float4(0.f, 0.f, 0.f, 0.f);
    } else if (le < 0) {
        v = make_float4(0.f, 0.f, 0.f, 0.f);
    } else if (sec == 0) {
        const int other = (r < NU) ? dst[le] : src[le];
        v = __ldg((const float4*)(otherArr + (size_t)other * 128 + c4));
    } else if (sec == 2) {
        const float tv = t[le];
        float4 f = __ldg((const float4*)(freq + c4));
        v.x = __cosf(tv * f.x); v.y = __cosf(tv * f.y);
        v.z = __cosf(tv * f.z); v.w = __cosf(tv * f.w);
    } else {
        v = __ldg((const float4*)(efeat + (size_t)le * 128 + c4));
    }

    uint2 p;
    p.x = h2u(__floats2half2_rn(v.x, v.y));
    p.y = h2u(__floats2half2_rn(v.z, v.w));
    *(uint2*)(d_X + (size_t)r * MDIM + sec * 128 + c4) = p;
}

// ---------------------------------------------------------------------------
__device__ __forceinline__ uint32_t smem_u32(const void* p) {
    uint32_t a;
    asm("{ .reg .u64 t; cvta.to.shared.u64 t, %1; cvt.u32.u64 %0, t; }" : "=r"(a) : "l"(p));
    return a;
}
__device__ __forceinline__ void cp16(uint32_t dst, const void* src) {
    asm volatile("cp.async.cg.shared.global [%0], [%1], 16;"
                 :: "r"(dst), "l"(src) : "memory");
}
#define CP_COMMIT() asm volatile("cp.async.commit_group;" ::: "memory")
#define CP_WAIT2()  asm volatile("cp.async.wait_group 2;" ::: "memory")

__device__ __forceinline__ void ldsm4(uint32_t& r0, uint32_t& r1, uint32_t& r2,
                                      uint32_t& r3, uint32_t a) {
    asm volatile("ldmatrix.sync.aligned.m8n8.x4.shared.b16 {%0,%1,%2,%3}, [%4];"
                 : "=r"(r0), "=r"(r1), "=r"(r2), "=r"(r3) : "r"(a));
}
__device__ __forceinline__ void mma_f16(float c[4], uint32_t a0, uint32_t a1,
                                        uint32_t a2, uint32_t a3,
                                        uint32_t b0, uint32_t b1) {
    asm volatile(
        "mma.sync.aligned.m16n8k16.row.col.f32.f16.f16.f32 "
        "{%0,%1,%2,%3}, {%4,%5,%6,%7}, {%8,%9}, {%0,%1,%2,%3};"
        : "+f"(c[0]), "+f"(c[1]), "+f"(c[2]), "+f"(c[3])
        : "r"(a0), "r"(a1), "r"(a2), "r"(a3), "r"(b0), "r"(b1));
}
__device__ __forceinline__ float sigf(float x) { return 1.f / (1.f + expf(-x)); }

// swizzled byte offset within one [128 rows x 32 halves] 8KB chunk
__device__ __forceinline__ uint32_t sw_off(int m, int u) {
    return (uint32_t)((m << 6) + (((u ^ ((m >> 1) & 3)) & 3) << 4));
}

// ---------------------------------------------------------------------------
// C[M,384] = A[M,K] @ B[384,K]^T, fp16/f32. 128x128 CTA tile, BK=32,
// 4-stage cp.async pipeline, ldmatrix, warp tile 64x32 (2x4 warps).
// GRID TRANSPOSED: blockIdx.x = n-tile (0..2), blockIdx.y = m-tile —
// the 3 n-tiles sharing an A m-tile are bid-adjacent -> same wave -> L2 reuse.
#define STG_BYTES 16384   // A 8KB + B 8KB per stage
#define SMEM_TOT  (4 * STG_BYTES)

__global__ __launch_bounds__(256, 2)
void k_hgemm(int sel, int K) {
    extern __shared__ char smraw[];
    const uint32_t sb = smem_u32(smraw);

    const __half* A  = sel ? d_H   : d_X;
    const __half* Bw = sel ? d_hWh : d_hWi;
    const int lda    = sel ? 128 : MDIM;
    float* C         = sel ? d_G2 : d_G1;

    const int tid  = threadIdx.x;
    const int lane = tid & 31;
    const int w    = tid >> 5;
    const int wm   = w & 1;
    const int wn   = w >> 1;
    const int g    = lane >> 2;
    const int tg   = lane & 3;
    const int m0   = blockIdx.y * 128;
    const int n0   = blockIdx.x * 128;

    const int lrow = tid >> 1;
    const int u0   = (tid & 1) * 2;
    const __half* aP = A  + (size_t)(m0 + lrow) * lda + u0 * 8;
    const __half* bP = Bw + (size_t)(n0 + lrow) * K   + u0 * 8;
    const uint32_t dA0 = sw_off(lrow, u0);
    const uint32_t dA1 = sw_off(lrow, u0 + 1);

    uint32_t offA[4][2], offB[2][2];
    {
        const int mr = ((lane >> 3) & 1) * 8 + (lane & 7);
        const int uu = lane >> 4;
#pragma unroll
        for (int im = 0; im < 4; ++im)
#pragma unroll
            for (int kk = 0; kk < 2; ++kk)
                offA[im][kk] = sw_off(wm * 64 + im * 16 + mr, kk * 2 + uu);
#pragma unroll
        for (int j = 0; j < 2; ++j)
#pragma unroll
            for (int kk = 0; kk < 2; ++kk)
                offB[j][kk] = 8192u + sw_off(wn * 32 + j * 16 + mr, kk * 2 + uu);
    }

    float acc[4][4][4];
#pragma unroll
    for (int i = 0; i < 4; ++i)
#pragma unroll
        for (int j = 0; j < 4; ++j)
#pragma unroll
            for (int c = 0; c < 4; ++c) acc[i][j][c] = 0.f;

    const int nch = K >> 5;

    // prologue: 3 stages in flight
#pragma unroll
    for (int s = 0; s < 3; ++s) {
        const uint32_t st = sb + s * STG_BYTES;
        cp16(st + dA0,        aP + s * 32);
        cp16(st + dA1,        aP + s * 32 + 8);
        cp16(st + 8192 + dA0, bP + s * 32);
        cp16(st + 8192 + dA1, bP + s * 32 + 8);
        CP_COMMIT();
    }

    for (int c = 0; c < nch; ++c) {
        CP_WAIT2();
        __syncthreads();

        if (c + 3 < nch) {
            const uint32_t st = sb + ((c + 3) & 3) * STG_BYTES;
            cp16(st + dA0,        aP + (c + 3) * 32);
            cp16(st + dA1,        aP + (c + 3) * 32 + 8);
            cp16(st + 8192 + dA0, bP + (c + 3) * 32);
            cp16(st + 8192 + dA1, bP + (c + 3) * 32 + 8);
        }
        CP_COMMIT();

        const uint32_t stg = sb + (c & 3) * STG_BYTES;
#pragma unroll
        for (int kk = 0; kk < 2; ++kk) {
            uint32_t a[4][4], b[2][4];
#pragma unroll
            for (int im = 0; im < 4; ++im)
                ldsm4(a[im][0], a[im][1], a[im][2], a[im][3], stg + offA[im][kk]);
#pragma unroll
            for (int j = 0; j < 2; ++j)
                ldsm4(b[j][0], b[j][1], b[j][2], b[j][3], stg + offB[j][kk]);
#pragma unroll
            for (int im = 0; im < 4; ++im) {
                mma_f16(acc[im][0], a[im][0], a[im][1], a[im][2], a[im][3],
                        b[0][0], b[0][2]);
                mma_f16(acc[im][1], a[im][0], a[im][1], a[im][2], a[im][3],
                        b[0][1], b[0][3]);
                mma_f16(acc[im][2], a[im][0], a[im][1], a[im][2], a[im][3],
                        b[1][0], b[1][2]);
                mma_f16(acc[im][3], a[im][0], a[im][1], a[im][2], a[im][3],
                        b[1][1], b[1][3]);
            }
        }
    }

    // epilogue
#pragma unroll
    for (int im = 0; im < 4; ++im) {
#pragma unroll
        for (int in_ = 0; in_ < 4; ++in_) {
            const int row = m0 + wm * 64 + im * 16 + g;
            const int col = n0 + wn * 32 + in_ * 8 + tg * 2;
            if (row < NROWS)
                *(float2*)(C + (size_t)row * G3 + col) =
                    make_float2(acc[im][in_][0], acc[im][in_][1]);
            if (row + 8 < NROWS)
                *(float2*)(C + (size_t)(row + 8) * G3 + col) =
                    make_float2(acc[im][in_][2], acc[im][in_][3]);
        }
    }
}

// ---------------------------------------------------------------------------
__global__ void k_combine(const float* __restrict__ si, const float* __restrict__ sj,
                          const float* __restrict__ bi, const float* __restrict__ bh,
                          float* __restrict__ out) {
    int r = blockIdx.x;
    int j = threadIdx.x;  // 0..127
    const float* g1 = d_G1 + (size_t)r * G3;
    const float* g2 = d_G2 + (size_t)r * G3;

    float h = (r < NU) ? si[(size_t)r * 128 + j] : sj[(size_t)(r - NU) * 128 + j];

    float gir = g1[j]       + bi[j];
    float giz = g1[j + 128] + bi[j + 128];
    float gin = g1[j + 256] + bi[j + 256];
    float ghr = g2[j]       + bh[j];
    float ghz = g2[j + 128] + bh[j + 128];
    float ghn = g2[j + 256] + bh[j + 256];

    float rr = sigf(gir + ghr);
    float zz = sigf(giz + ghz);
    float nn = tanhf(gin + rr * ghn);

    out[(size_t)r * 128 + j] = (1.f - zz) * nn + zz * h;
}

// ---------------------------------------------------------------------------
extern "C" void kernel_launch(void* const* d_in, const int* in_sizes, int n_in,
                              void* d_out, int out_size) {
    const float* si   = (const float*)d_in[0];
    const float* sj   = (const float*)d_in[1];
    const float* t    = (const float*)d_in[2];
    const float* ef   = (const float*)d_in[3];
    const int*   src  = (const int*)d_in[4];
    const int*   dst  = (const int*)d_in[5];
    const float* Wi   = (const float*)d_in[6];
    const float* Wh   = (const float*)d_in[7];
    const float* bi   = (const float*)d_in[8];
    const float* bh   = (const float*)d_in[9];
    const float* freq = (const float*)d_in[10];
    float* out = (float*)d_out;

    k_init_last<<<(NU + 255) / 256, 256>>>();
    k_scan_edges<<<(NE + 255) / 256, 256>>>(src, dst);
    k_cvt_w<<<(G3 * MDIM + 255) / 256, 256>>>(Wi, Wh);
    k_build_x<<<NROWS, 128>>>(si, sj, t, ef, src, dst, freq);

    cudaFuncSetAttribute(k_hgemm, cudaFuncAttributeMaxDynamicSharedMemorySize, SMEM_TOT);
    dim3 grid(3, NPAD / 128);                    // n fastest -> A m-tile L2 reuse
    k_hgemm<<<grid, 256, SMEM_TOT>>>(0, MDIM);   // G1 = X @ Wi^T
    k_hgemm<<<grid, 256, SMEM_TOT>>>(1, 128);    // G2 = H @ Wh^T

    k_combine<<<NROWS, 128>>>(si, sj, bi, bh, out);
}

// round 11
// speedup vs baseline: 1.2674x; 1.0536x over previous
#include <cuda_runtime.h>
#include <cuda_fp16.h>
#include <math.h>
#include <stdint.h>

#define NU 100000
#define NI 100000
#define NE 300000
#define NROWS (NU + NI)
#define NPAD 200064            // 1563 * 128
#define G3 384
#define MDIM 512

__device__ int    d_lastU[NU];
__device__ int    d_lastV[NI];
__device__ __half d_X[(size_t)NPAD * MDIM];   // mail fp16 (padded rows stay 0)
__device__ __half d_H[(size_t)NPAD * 128];    // h fp16
__device__ __half d_hWi[G3 * MDIM];
__device__ __half d_hWh[G3 * 128];
__device__ __half d_G1[(size_t)NROWS * G3];   // fp16 gate buffer (153 MB)
__device__ __half d_G2[(size_t)NROWS * G3];   // fp16 gate buffer (153 MB)

// ---------------------------------------------------------------------------
__global__ void k_init_last() {
    int i = blockIdx.x * blockDim.x + threadIdx.x;
    if (i < NU) d_lastU[i] = -1;
    if (i < NI) d_lastV[i] = -1;
}

__global__ void k_scan_edges(const int* __restrict__ src, const int* __restrict__ dst) {
    int i = blockIdx.x * blockDim.x + threadIdx.x;
    if (i < NE) {
        atomicMax(&d_lastU[src[i]], i);
        atomicMax(&d_lastV[dst[i]], i);
    }
}

__global__ void k_cvt_w(const float* __restrict__ Wi, const float* __restrict__ Wh) {
    int i = blockIdx.x * blockDim.x + threadIdx.x;
    if (i < G3 * MDIM) d_hWi[i] = __float2half(Wi[i]);
    if (i < G3 * 128)  d_hWh[i] = __float2half(Wh[i]);
}

__device__ __forceinline__ uint32_t h2u(__half2 h) { return *(uint32_t*)&h; }

// K2: build X rows (fp16, vectorized 8B stores) + H rows (fp16).
__global__ void k_build_x(const float* __restrict__ si, const float* __restrict__ sj,
                          const float* __restrict__ t,  const float* __restrict__ efeat,
                          const int* __restrict__ src,  const int* __restrict__ dst,
                          const float* __restrict__ freq) {
    const int r   = blockIdx.x;
    const int tid = threadIdx.x;      // 0..127
    const int sec = tid >> 5;         // 0..3
    const int c4  = (tid & 31) * 4;   // col within section

    int le;
    const float* ownbase;
    const float* otherArr;
    if (r < NU) {
        le = d_lastU[r];
        ownbase = si + (size_t)r * 128;
        otherArr = sj;
    } else {
        le = d_lastV[r - NU];
        ownbase = sj + (size_t)(r - NU) * 128;
        otherArr = si;
    }

    float4 v;
    if (sec == 1) {
        v = __ldg((const float4*)(ownbase + c4));
        uint2 hh;
        hh.x = h2u(__floats2half2_rn(v.x, v.y));
        hh.y = h2u(__floats2half2_rn(v.z, v.w));
        *(uint2*)(d_H + (size_t)r * 128 + c4) = hh;
        if (le < 0) v = make_float4(0.f, 0.f, 0.f, 0.f);
    } else if (le < 0) {
        v = make_float4(0.f, 0.f, 0.f, 0.f);
    } else if (sec == 0) {
        const int other = (r < NU) ? dst[le] : src[le];
        v = __ldg((const float4*)(otherArr + (size_t)other * 128 + c4));
    } else if (sec == 2) {
        const float tv = t[le];
        float4 f = __ldg((const float4*)(freq + c4));
        v.x = __cosf(tv * f.x); v.y = __cosf(tv * f.y);
        v.z = __cosf(tv * f.z); v.w = __cosf(tv * f.w);
    } else {
        v = __ldg((const float4*)(efeat + (size_t)le * 128 + c4));
    }

    uint2 p;
    p.x = h2u(__floats2half2_rn(v.x, v.y));
    p.y = h2u(__floats2half2_rn(v.z, v.w));
    *(uint2*)(d_X + (size_t)r * MDIM + sec * 128 + c4) = p;
}

// ---------------------------------------------------------------------------
__device__ __forceinline__ uint32_t smem_u32(const void* p) {
    uint32_t a;
    asm("{ .reg .u64 t; cvta.to.shared.u64 t, %1; cvt.u32.u64 %0, t; }" : "=r"(a) : "l"(p));
    return a;
}
__device__ __forceinline__ void cp16(uint32_t dst, const void* src) {
    asm volatile("cp.async.cg.shared.global [%0], [%1], 16;"
                 :: "r"(dst), "l"(src) : "memory");
}
#define CP_COMMIT() asm volatile("cp.async.commit_group;" ::: "memory")
#define CP_WAIT2()  asm volatile("cp.async.wait_group 2;" ::: "memory")

__device__ __forceinline__ void ldsm4(uint32_t& r0, uint32_t& r1, uint32_t& r2,
                                      uint32_t& r3, uint32_t a) {
    asm volatile("ldmatrix.sync.aligned.m8n8.x4.shared.b16 {%0,%1,%2,%3}, [%4];"
                 : "=r"(r0), "=r"(r1), "=r"(r2), "=r"(r3) : "r"(a));
}
__device__ __forceinline__ void mma_f16(float c[4], uint32_t a0, uint32_t a1,
                                        uint32_t a2, uint32_t a3,
                                        uint32_t b0, uint32_t b1) {
    asm volatile(
        "mma.sync.aligned.m16n8k16.row.col.f32.f16.f16.f32 "
        "{%0,%1,%2,%3}, {%4,%5,%6,%7}, {%8,%9}, {%0,%1,%2,%3};"
        : "+f"(c[0]), "+f"(c[1]), "+f"(c[2]), "+f"(c[3])
        : "r"(a0), "r"(a1), "r"(a2), "r"(a3), "r"(b0), "r"(b1));
}
__device__ __forceinline__ float sigf(float x) { return 1.f / (1.f + expf(-x)); }

// swizzled byte offset within one [128 rows x 32 halves] 8KB chunk
__device__ __forceinline__ uint32_t sw_off(int m, int u) {
    return (uint32_t)((m << 6) + (((u ^ ((m >> 1) & 3)) & 3) << 4));
}

// ---------------------------------------------------------------------------
// C[M,384] = A[M,K] @ B[384,K]^T, fp16 operands, f32 accum, fp16 C store.
// 128x128 CTA tile, BK=32, 4-stage cp.async, ldmatrix, warp tile 64x32.
// grid (3, m-tiles): the 3 n-tiles sharing an A m-tile are bid-adjacent.
#define STG_BYTES 16384
#define SMEM_TOT  (4 * STG_BYTES)

__global__ __launch_bounds__(256, 2)
void k_hgemm(int sel, int K) {
    extern __shared__ char smraw[];
    const uint32_t sb = smem_u32(smraw);

    const __half* A  = sel ? d_H   : d_X;
    const __half* Bw = sel ? d_hWh : d_hWi;
    const int lda    = sel ? 128 : MDIM;
    __half* C        = sel ? d_G2 : d_G1;

    const int tid  = threadIdx.x;
    const int lane = tid & 31;
    const int w    = tid >> 5;
    const int wm   = w & 1;
    const int wn   = w >> 1;
    const int g    = lane >> 2;
    const int tg   = lane & 3;
    const int m0   = blockIdx.y * 128;
    const int n0   = blockIdx.x * 128;

    const int lrow = tid >> 1;
    const int u0   = (tid & 1) * 2;
    const __half* aP = A  + (size_t)(m0 + lrow) * lda + u0 * 8;
    const __half* bP = Bw + (size_t)(n0 + lrow) * K   + u0 * 8;
    const uint32_t dA0 = sw_off(lrow, u0);
    const uint32_t dA1 = sw_off(lrow, u0 + 1);

    uint32_t offA[4][2], offB[2][2];
    {
        const int mr = ((lane >> 3) & 1) * 8 + (lane & 7);
        const int uu = lane >> 4;
#pragma unroll
        for (int im = 0; im < 4; ++im)
#pragma unroll
            for (int kk = 0; kk < 2; ++kk)
                offA[im][kk] = sw_off(wm * 64 + im * 16 + mr, kk * 2 + uu);
#pragma unroll
        for (int j = 0; j < 2; ++j)
#pragma unroll
            for (int kk = 0; kk < 2; ++kk)
                offB[j][kk] = 8192u + sw_off(wn * 32 + j * 16 + mr, kk * 2 + uu);
    }

    float acc[4][4][4];
#pragma unroll
    for (int i = 0; i < 4; ++i)
#pragma unroll
        for (int j = 0; j < 4; ++j)
#pragma unroll
            for (int c = 0; c < 4; ++c) acc[i][j][c] = 0.f;

    const int nch = K >> 5;

#pragma unroll
    for (int s = 0; s < 3; ++s) {
        const uint32_t st = sb + s * STG_BYTES;
        cp16(st + dA0,        aP + s * 32);
        cp16(st + dA1,        aP + s * 32 + 8);
        cp16(st + 8192 + dA0, bP + s * 32);
        cp16(st + 8192 + dA1, bP + s * 32 + 8);
        CP_COMMIT();
    }

    for (int c = 0; c < nch; ++c) {
        CP_WAIT2();
        __syncthreads();

        if (c + 3 < nch) {
            const uint32_t st = sb + ((c + 3) & 3) * STG_BYTES;
            cp16(st + dA0,        aP + (c + 3) * 32);
            cp16(st + dA1,        aP + (c + 3) * 32 + 8);
            cp16(st + 8192 + dA0, bP + (c + 3) * 32);
            cp16(st + 8192 + dA1, bP + (c + 3) * 32 + 8);
        }
        CP_COMMIT();

        const uint32_t stg = sb + (c & 3) * STG_BYTES;
#pragma unroll
        for (int kk = 0; kk < 2; ++kk) {
            uint32_t a[4][4], b[2][4];
#pragma unroll
            for (int im = 0; im < 4; ++im)
                ldsm4(a[im][0], a[im][1], a[im][2], a[im][3], stg + offA[im][kk]);
#pragma unroll
            for (int j = 0; j < 2; ++j)
                ldsm4(b[j][0], b[j][1], b[j][2], b[j][3], stg + offB[j][kk]);
#pragma unroll
            for (int im = 0; im < 4; ++im) {
                mma_f16(acc[im][0], a[im][0], a[im][1], a[im][2], a[im][3],
                        b[0][0], b[0][2]);
                mma_f16(acc[im][1], a[im][0], a[im][1], a[im][2], a[im][3],
                        b[0][1], b[0][3]);
                mma_f16(acc[im][2], a[im][0], a[im][1], a[im][2], a[im][3],
                        b[1][0], b[1][2]);
                mma_f16(acc[im][3], a[im][0], a[im][1], a[im][2], a[im][3],
                        b[1][1], b[1][3]);
            }
        }
    }

    // epilogue: fp16 store (half2 per row-pair entry)
#pragma unroll
    for (int im = 0; im < 4; ++im) {
#pragma unroll
        for (int in_ = 0; in_ < 4; ++in_) {
            const int row = m0 + wm * 64 + im * 16 + g;
            const int col = n0 + wn * 32 + in_ * 8 + tg * 2;
            if (row < NROWS)
                *(__half2*)(C + (size_t)row * G3 + col) =
                    __floats2half2_rn(acc[im][in_][0], acc[im][in_][1]);
            if (row + 8 < NROWS)
                *(__half2*)(C + (size_t)(row + 8) * G3 + col) =
                    __floats2half2_rn(acc[im][in_][2], acc[im][in_][3]);
        }
    }
}

// ---------------------------------------------------------------------------
// Combine: 4 rows per 256-thread CTA, 64 threads per row, half2/float2 loads.
__device__ __forceinline__ float2 ldh2(const __half* p) {
    return __half22float2(*(const __half2*)p);
}

__global__ void k_combine(const float* __restrict__ si, const float* __restrict__ sj,
                          const float* __restrict__ bi, const float* __restrict__ bh,
                          float* __restrict__ out) {
    const int r = blockIdx.x * 4 + (threadIdx.x >> 6);
    const int j = (threadIdx.x & 63) * 2;

    const __half* g1 = d_G1 + (size_t)r * G3;
    const __half* g2 = d_G2 + (size_t)r * G3;
    const float* hp = (r < NU) ? si + (size_t)r * 128 : sj + (size_t)(r - NU) * 128;

    float2 g1r = ldh2(g1 + j);
    float2 g1z = ldh2(g1 + 128 + j);
    float2 g1n = ldh2(g1 + 256 + j);
    float2 g2r = ldh2(g2 + j);
    float2 g2z = ldh2(g2 + 128 + j);
    float2 g2n = ldh2(g2 + 256 + j);

    float2 bir = __ldg((const float2*)(bi + j));
    float2 biz = __ldg((const float2*)(bi + 128 + j));
    float2 bin = __ldg((const float2*)(bi + 256 + j));
    float2 bhr = __ldg((const float2*)(bh + j));
    float2 bhz = __ldg((const float2*)(bh + 128 + j));
    float2 bhn = __ldg((const float2*)(bh + 256 + j));

    float2 hv = *(const float2*)(hp + j);

    float r0 = sigf(g1r.x + bir.x + g2r.x + bhr.x);
    float r1 = sigf(g1r.y + bir.y + g2r.y + bhr.y);
    float z0 = sigf(g1z.x + biz.x + g2z.x + bhz.x);
    float z1 = sigf(g1z.y + biz.y + g2z.y + bhz.y);
    float n0 = tanhf(g1n.x + bin.x + r0 * (g2n.x + bhn.x));
    float n1 = tanhf(g1n.y + bin.y + r1 * (g2n.y + bhn.y));

    float2 o;
    o.x = (1.f - z0) * n0 + z0 * hv.x;
    o.y = (1.f - z1) * n1 + z1 * hv.y;
    *(float2*)(out + (size_t)r * 128 + j) = o;
}

// ---------------------------------------------------------------------------
extern "C" void kernel_launch(void* const* d_in, const int* in_sizes, int n_in,
                              void* d_out, int out_size) {
    const float* si   = (const float*)d_in[0];
    const float* sj   = (const float*)d_in[1];
    const float* t    = (const float*)d_in[2];
    const float* ef   = (const float*)d_in[3];
    const int*   src  = (const int*)d_in[4];
    const int*   dst  = (const int*)d_in[5];
    const float* Wi   = (const float*)d_in[6];
    const float* Wh   = (const float*)d_in[7];
    const float* bi   = (const float*)d_in[8];
    const float* bh   = (const float*)d_in[9];
    const float* freq = (const float*)d_in[10];
    float* out = (float*)d_out;

    k_init_last<<<(NU + 255) / 256, 256>>>();
    k_scan_edges<<<(NE + 255) / 256, 256>>>(src, dst);
    k_cvt_w<<<(G3 * MDIM + 255) / 256, 256>>>(Wi, Wh);
    k_build_x<<<NROWS, 128>>>(si, sj, t, ef, src, dst, freq);

    cudaFuncSetAttribute(k_hgemm, cudaFuncAttributeMaxDynamicSharedMemorySize, SMEM_TOT);
    dim3 grid(3, NPAD / 128);
    k_hgemm<<<grid, 256, SMEM_TOT>>>(0, MDIM);   // G1 = X @ Wi^T
    k_hgemm<<<grid, 256, SMEM_TOT>>>(1, 128);    // G2 = H @ Wh^T

    k_combine<<<NROWS / 4, 256>>>(si, sj, bi, bh, out);
}